// round 2
// baseline (speedup 1.0000x reference)
#include <cuda_runtime.h>
#include <math.h>

// Problem constants
#define W_DIM   512
#define IN_CH   512
#define OUT_CH  3
#define BATCH   32
#define HW      16384          // 128*128 pixels per (b, channel) plane
#define HW4     4096           // pixels / 4 (float4 granularity)
#define CLAMP_V 256.0f

// Scratch for per-(batch, channel) styles. 32*512 floats = 64 KB.
__device__ float g_styles[BATCH * IN_CH];

__device__ __forceinline__ float clampf(float v) {
    return fminf(fmaxf(v, -CLAMP_V), CLAMP_V);
}

// ---------------------------------------------------------------------------
// Kernel 1: styles[b,i] = (dot(w[b,:], aw[i,:]) * fc_gain + ab[i]) * weight_gain
// One warp per output channel i; lanes split the 512-long dot as 4 float4 chunks.
// ---------------------------------------------------------------------------
__global__ void __launch_bounds__(256) styles_kernel(
    const float* __restrict__ w,    // (32, 512)
    const float* __restrict__ aw,   // (512, 512)
    const float* __restrict__ ab)   // (512,)
{
    const int warp = (blockIdx.x * blockDim.x + threadIdx.x) >> 5;
    const int lane = threadIdx.x & 31;
    if (warp >= IN_CH) return;
    const int i = warp;

    const float4* aw4 = (const float4*)(aw + (size_t)i * W_DIM);
    float4 av[4];
#pragma unroll
    for (int c = 0; c < 4; c++) av[c] = aw4[c * 32 + lane];

    const float fc_gain     = 1.0f / sqrtf((float)W_DIM);
    const float weight_gain = 1.0f / sqrtf((float)IN_CH);
    const float abi = ab[i];

    for (int b = 0; b < BATCH; b++) {
        const float4* w4 = (const float4*)(w + (size_t)b * W_DIM);
        float p = 0.0f;
#pragma unroll
        for (int c = 0; c < 4; c++) {
            float4 wv = w4[c * 32 + lane];
            p += av[c].x * wv.x + av[c].y * wv.y + av[c].z * wv.z + av[c].w * wv.w;
        }
#pragma unroll
        for (int off = 16; off; off >>= 1)
            p += __shfl_xor_sync(0xffffffffu, p, off);
        if (lane == 0)
            g_styles[b * IN_CH + i] = (p * fc_gain + abi) * weight_gain;
    }
}

// ---------------------------------------------------------------------------
// Kernel 2: out[b,o,p] = clip( sum_i x[b,i,p] * (wk[o,i]*styles[b,i]) + bias[o] )
// grid = (16, 32): blockIdx.y = batch, blockIdx.x = pixel chunk.
// Each thread owns one float4 (4 pixels). sw[o][i] premultiplied into shared.
// Unroll-8 channel loop -> 8 independent coalesced LDG.128 in flight.
// ---------------------------------------------------------------------------
__global__ void __launch_bounds__(256) torgb_kernel(
    const float* __restrict__ x,     // (32, 512, 128, 128)
    const float* __restrict__ wk,    // (3, 512) -- weight[:,:,0,0] contiguous
    const float* __restrict__ bias,  // (3,)
    float*       __restrict__ out)   // (32, 3, 128, 128)
{
    __shared__ float sw[OUT_CH * IN_CH];   // 6 KB

    const int b = blockIdx.y;
    const float* st = g_styles + (size_t)b * IN_CH;

    for (int idx = threadIdx.x; idx < OUT_CH * IN_CH; idx += blockDim.x)
        sw[idx] = wk[idx] * st[idx & (IN_CH - 1)];
    __syncthreads();

    const int p = blockIdx.x * blockDim.x + threadIdx.x;   // 0..4095 float4 index
    const float4* xb = (const float4*)x + (size_t)b * IN_CH * HW4 + p;

    float4 a0 = {0.f, 0.f, 0.f, 0.f};
    float4 a1 = a0;
    float4 a2 = a0;

#pragma unroll 8
    for (int i = 0; i < IN_CH; i++) {
        float4 xv = xb[(size_t)i * HW4];
        float s0 = sw[i];
        float s1 = sw[IN_CH + i];
        float s2 = sw[2 * IN_CH + i];
        a0.x = fmaf(s0, xv.x, a0.x); a0.y = fmaf(s0, xv.y, a0.y);
        a0.z = fmaf(s0, xv.z, a0.z); a0.w = fmaf(s0, xv.w, a0.w);
        a1.x = fmaf(s1, xv.x, a1.x); a1.y = fmaf(s1, xv.y, a1.y);
        a1.z = fmaf(s1, xv.z, a1.z); a1.w = fmaf(s1, xv.w, a1.w);
        a2.x = fmaf(s2, xv.x, a2.x); a2.y = fmaf(s2, xv.y, a2.y);
        a2.z = fmaf(s2, xv.z, a2.z); a2.w = fmaf(s2, xv.w, a2.w);
    }

    const float b0 = bias[0], b1 = bias[1], b2 = bias[2];

    float4 r0, r1, r2;
    r0.x = clampf(a0.x + b0); r0.y = clampf(a0.y + b0);
    r0.z = clampf(a0.z + b0); r0.w = clampf(a0.w + b0);
    r1.x = clampf(a1.x + b1); r1.y = clampf(a1.y + b1);
    r1.z = clampf(a1.z + b1); r1.w = clampf(a1.w + b1);
    r2.x = clampf(a2.x + b2); r2.y = clampf(a2.y + b2);
    r2.z = clampf(a2.z + b2); r2.w = clampf(a2.w + b2);

    float4* ob = (float4*)out + (size_t)b * OUT_CH * HW4 + p;
    ob[0]       = r0;
    ob[HW4]     = r1;
    ob[2 * HW4] = r2;
}

// ---------------------------------------------------------------------------
// kernel_launch
// Input order (metadata): x, w, affine_weight, affine_bias, weight, bias
// ---------------------------------------------------------------------------
extern "C" void kernel_launch(void* const* d_in, const int* in_sizes, int n_in,
                              void* d_out, int out_size)
{
    const float* x    = (const float*)d_in[0];
    const float* w    = (const float*)d_in[1];
    const float* aw   = (const float*)d_in[2];
    const float* ab   = (const float*)d_in[3];
    const float* wk   = (const float*)d_in[4];  // (3,512,1,1) contiguous == (3,512)
    const float* bias = (const float*)d_in[5];
    float* out = (float*)d_out;

    // Kernel 1: 512 warps -> 64 blocks of 256 threads
    styles_kernel<<<64, 256>>>(w, aw, ab);

    // Kernel 2: (pixel chunks, batch)
    dim3 grid(HW4 / 256, BATCH);
    torgb_kernel<<<grid, 256>>>(x, wk, bias, out);
}

// round 4
// speedup vs baseline: 1.0841x; 1.0841x over previous
#include <cuda_runtime.h>
#include <math.h>

// Problem constants
#define W_DIM   512
#define IN_CH   512
#define OUT_CH  3
#define BATCH   32
#define HW      16384          // 128*128 pixels per (b, channel) plane
#define HW4     4096           // pixels / 4 (float4 granularity)
#define CLAMP_V 256.0f

// Scratch for per-(batch, channel) styles. 32*512 floats = 64 KB.
__device__ float g_styles[BATCH * IN_CH];

__device__ __forceinline__ float clampf(float v) {
    return fminf(fmaxf(v, -CLAMP_V), CLAMP_V);
}

// ---------------------------------------------------------------------------
// Kernel 1: styles[b,i] = (dot(w[b,:], aw[i,:]) * fc_gain + ab[i]) * weight_gain
// Warp per (channel i, batch-group of 8). 2048 warps total -> 4x less serial
// work per warp than warp-per-channel. aw row loads fully coalesced.
// ---------------------------------------------------------------------------
#define BGROUPS 4
#define B_PER_G (BATCH / BGROUPS)   // 8

__global__ void __launch_bounds__(256) styles_kernel(
    const float* __restrict__ w,    // (32, 512)
    const float* __restrict__ aw,   // (512, 512)
    const float* __restrict__ ab)   // (512,)
{
    const int warp = (blockIdx.x * blockDim.x + threadIdx.x) >> 5;
    const int lane = threadIdx.x & 31;
    const int i  = warp >> 2;          // channel 0..511
    const int bg = warp & 3;           // batch group 0..3
    if (i >= IN_CH) return;

    const float4* aw4 = (const float4*)(aw + (size_t)i * W_DIM);
    float4 av[4];
#pragma unroll
    for (int c = 0; c < 4; c++) av[c] = aw4[c * 32 + lane];

    const float fc_gain     = 1.0f / sqrtf((float)W_DIM);
    const float weight_gain = 1.0f / sqrtf((float)IN_CH);
    const float abi = ab[i];

#pragma unroll
    for (int bb = 0; bb < B_PER_G; bb++) {
        const int b = bg * B_PER_G + bb;
        const float4* w4 = (const float4*)(w + (size_t)b * W_DIM);
        float p = 0.0f;
#pragma unroll
        for (int c = 0; c < 4; c++) {
            float4 wv = w4[c * 32 + lane];
            p += av[c].x * wv.x + av[c].y * wv.y + av[c].z * wv.z + av[c].w * wv.w;
        }
#pragma unroll
        for (int off = 16; off; off >>= 1)
            p += __shfl_xor_sync(0xffffffffu, p, off);
        if (lane == 0)
            g_styles[b * IN_CH + i] = (p * fc_gain + abi) * weight_gain;
    }
}

// ---------------------------------------------------------------------------
// Kernel 2: out[b,o,p] = clip( sum_i x[b,i,p] * (wk[o,i]*styles[b,i]) + bias[o] )
// grid = (16, 32): blockIdx.y = batch, blockIdx.x = pixel chunk.
// Each thread owns one float4 (4 pixels). sw[o][i] premultiplied into shared.
// Unroll-8 channel loop -> 8 independent coalesced LDG.128 in flight.
// This kernel runs at the achieved-HBM ceiling (~6.2 TB/s); leave it alone.
// ---------------------------------------------------------------------------
__global__ void __launch_bounds__(256) torgb_kernel(
    const float* __restrict__ x,     // (32, 512, 128, 128)
    const float* __restrict__ wk,    // (3, 512) -- weight[:,:,0,0] contiguous
    const float* __restrict__ bias,  // (3,)
    float*       __restrict__ out)   // (32, 3, 128, 128)
{
    __shared__ float sw[OUT_CH * IN_CH];   // 6 KB

    const int b = blockIdx.y;
    const float* st = g_styles + (size_t)b * IN_CH;

    for (int idx = threadIdx.x; idx < OUT_CH * IN_CH; idx += blockDim.x)
        sw[idx] = wk[idx] * st[idx & (IN_CH - 1)];
    __syncthreads();

    const int p = blockIdx.x * blockDim.x + threadIdx.x;   // 0..4095 float4 index
    const float4* xb = (const float4*)x + (size_t)b * IN_CH * HW4 + p;

    float4 a0 = {0.f, 0.f, 0.f, 0.f};
    float4 a1 = a0;
    float4 a2 = a0;

#pragma unroll 8
    for (int i = 0; i < IN_CH; i++) {
        float4 xv = xb[(size_t)i * HW4];
        float s0 = sw[i];
        float s1 = sw[IN_CH + i];
        float s2 = sw[2 * IN_CH + i];
        a0.x = fmaf(s0, xv.x, a0.x); a0.y = fmaf(s0, xv.y, a0.y);
        a0.z = fmaf(s0, xv.z, a0.z); a0.w = fmaf(s0, xv.w, a0.w);
        a1.x = fmaf(s1, xv.x, a1.x); a1.y = fmaf(s1, xv.y, a1.y);
        a1.z = fmaf(s1, xv.z, a1.z); a1.w = fmaf(s1, xv.w, a1.w);
        a2.x = fmaf(s2, xv.x, a2.x); a2.y = fmaf(s2, xv.y, a2.y);
        a2.z = fmaf(s2, xv.z, a2.z); a2.w = fmaf(s2, xv.w, a2.w);
    }

    const float b0 = bias[0], b1 = bias[1], b2 = bias[2];

    float4 r0, r1, r2;
    r0.x = clampf(a0.x + b0); r0.y = clampf(a0.y + b0);
    r0.z = clampf(a0.z + b0); r0.w = clampf(a0.w + b0);
    r1.x = clampf(a1.x + b1); r1.y = clampf(a1.y + b1);
    r1.z = clampf(a1.z + b1); r1.w = clampf(a1.w + b1);
    r2.x = clampf(a2.x + b2); r2.y = clampf(a2.y + b2);
    r2.z = clampf(a2.z + b2); r2.w = clampf(a2.w + b2);

    float4* ob = (float4*)out + (size_t)b * OUT_CH * HW4 + p;
    ob[0]       = r0;
    ob[HW4]     = r1;
    ob[2 * HW4] = r2;
}

// ---------------------------------------------------------------------------
// kernel_launch
// Input order (metadata): x, w, affine_weight, affine_bias, weight, bias
// ---------------------------------------------------------------------------
extern "C" void kernel_launch(void* const* d_in, const int* in_sizes, int n_in,
                              void* d_out, int out_size)
{
    const float* x    = (const float*)d_in[0];
    const float* w    = (const float*)d_in[1];
    const float* aw   = (const float*)d_in[2];
    const float* ab   = (const float*)d_in[3];
    const float* wk   = (const float*)d_in[4];  // (3,512,1,1) contiguous == (3,512)
    const float* bias = (const float*)d_in[5];
    float* out = (float*)d_out;

    // Kernel 1: 2048 warps (512 channels x 4 batch groups) -> 256 blocks
    styles_kernel<<<256, 256>>>(w, aw, ab);

    // Kernel 2: (pixel chunks, batch)
    dim3 grid(HW4 / 256, BATCH);
    torgb_kernel<<<grid, 256>>>(x, wk, bias, out);
}

// round 6
// speedup vs baseline: 1.1606x; 1.0705x over previous
#include <cuda_runtime.h>
#include <math.h>

// Problem constants
#define W_DIM   512
#define IN_CH   512
#define OUT_CH  3
#define BATCH   32
#define HW      16384          // 128*128 pixels per (b, channel) plane
#define HW4     4096           // pixels / 4 (float4 granularity)
#define CLAMP_V 256.0f

// Scratch for per-(batch, channel) styles. 32*512 floats = 64 KB.
__device__ float g_styles[BATCH * IN_CH];

__device__ __forceinline__ float clampf(float v) {
    return fminf(fmaxf(v, -CLAMP_V), CLAMP_V);
}

// ---------------------------------------------------------------------------
// Kernel 1: styles[b,i] = (dot(w[b,:], aw[i,:]) * fc_gain + ab[i]) * weight_gain
// Fully parallel: one warp per (channel i, batch b) -> 16384 warps, no serial
// batch loop. aw rows re-read per batch but L2-hot (1 MB working set).
// ---------------------------------------------------------------------------
__global__ void __launch_bounds__(256) styles_kernel(
    const float* __restrict__ w,    // (32, 512)
    const float* __restrict__ aw,   // (512, 512)
    const float* __restrict__ ab)   // (512,)
{
    const int warp = (blockIdx.x * blockDim.x + threadIdx.x) >> 5;
    const int lane = threadIdx.x & 31;
    const int i = warp >> 5;           // channel 0..511
    const int b = warp & 31;           // batch   0..31

    if (i < IN_CH) {
        const float4* aw4 = (const float4*)(aw + (size_t)i * W_DIM);
        const float4* w4  = (const float4*)(w  + (size_t)b * W_DIM);

        float p = 0.0f;
#pragma unroll
        for (int c = 0; c < 4; c++) {
            float4 av = aw4[c * 32 + lane];
            float4 wv = w4[c * 32 + lane];
            p += av.x * wv.x + av.y * wv.y + av.z * wv.z + av.w * wv.w;
        }
#pragma unroll
        for (int off = 16; off; off >>= 1)
            p += __shfl_xor_sync(0xffffffffu, p, off);

        if (lane == 0) {
            const float fc_gain     = 1.0f / sqrtf((float)W_DIM);
            const float weight_gain = 1.0f / sqrtf((float)IN_CH);
            g_styles[b * IN_CH + i] = (p * fc_gain + ab[i]) * weight_gain;
        }
    }

    // Release the dependent (PDL) kernel as soon as our writes are done.
    cudaTriggerProgrammaticLaunchCompletion();
}

// ---------------------------------------------------------------------------
// Kernel 2: out[b,o,p] = clip( sum_i x[b,i,p] * (wk[o,i]*styles[b,i]) + bias[o] )
// Launched with programmatic dependent launch: prologue (index math, bias
// loads) overlaps styles_kernel; cudaGridDependencySynchronize() gates the
// g_styles read. Streaming phase runs at the achieved-HBM ceiling (~6.27 TB/s).
// ---------------------------------------------------------------------------
__global__ void __launch_bounds__(256) torgb_kernel(
    const float* __restrict__ x,     // (32, 512, 128, 128)
    const float* __restrict__ wk,    // (3, 512) -- weight[:,:,0,0] contiguous
    const float* __restrict__ bias,  // (3,)
    float*       __restrict__ out)   // (32, 3, 128, 128)
{
    __shared__ float sw[OUT_CH * IN_CH];   // 6 KB

    const int b = blockIdx.y;
    const int p = blockIdx.x * blockDim.x + threadIdx.x;   // 0..4095 float4 index
    const float4* xb = (const float4*)x + (size_t)b * IN_CH * HW4 + p;
    const float* st = g_styles + (size_t)b * IN_CH;

    const float b0 = bias[0], b1 = bias[1], b2 = bias[2];

    // Wait for styles_kernel's results before reading g_styles.
    cudaGridDependencySynchronize();

    for (int idx = threadIdx.x; idx < OUT_CH * IN_CH; idx += blockDim.x)
        sw[idx] = wk[idx] * st[idx & (IN_CH - 1)];
    __syncthreads();

    float4 a0 = {0.f, 0.f, 0.f, 0.f};
    float4 a1 = a0;
    float4 a2 = a0;

#pragma unroll 8
    for (int i = 0; i < IN_CH; i++) {
        float4 xv = xb[(size_t)i * HW4];
        float s0 = sw[i];
        float s1 = sw[IN_CH + i];
        float s2 = sw[2 * IN_CH + i];
        a0.x = fmaf(s0, xv.x, a0.x); a0.y = fmaf(s0, xv.y, a0.y);
        a0.z = fmaf(s0, xv.z, a0.z); a0.w = fmaf(s0, xv.w, a0.w);
        a1.x = fmaf(s1, xv.x, a1.x); a1.y = fmaf(s1, xv.y, a1.y);
        a1.z = fmaf(s1, xv.z, a1.z); a1.w = fmaf(s1, xv.w, a1.w);
        a2.x = fmaf(s2, xv.x, a2.x); a2.y = fmaf(s2, xv.y, a2.y);
        a2.z = fmaf(s2, xv.z, a2.z); a2.w = fmaf(s2, xv.w, a2.w);
    }

    float4 r0, r1, r2;
    r0.x = clampf(a0.x + b0); r0.y = clampf(a0.y + b0);
    r0.z = clampf(a0.z + b0); r0.w = clampf(a0.w + b0);
    r1.x = clampf(a1.x + b1); r1.y = clampf(a1.y + b1);
    r1.z = clampf(a1.z + b1); r1.w = clampf(a1.w + b1);
    r2.x = clampf(a2.x + b2); r2.y = clampf(a2.y + b2);
    r2.z = clampf(a2.z + b2); r2.w = clampf(a2.w + b2);

    float4* ob = (float4*)out + (size_t)b * OUT_CH * HW4 + p;
    ob[0]       = r0;
    ob[HW4]     = r1;
    ob[2 * HW4] = r2;
}

// ---------------------------------------------------------------------------
// kernel_launch
// Input order (metadata): x, w, affine_weight, affine_bias, weight, bias
// ---------------------------------------------------------------------------
extern "C" void kernel_launch(void* const* d_in, const int* in_sizes, int n_in,
                              void* d_out, int out_size)
{
    const float* x    = (const float*)d_in[0];
    const float* w    = (const float*)d_in[1];
    const float* aw   = (const float*)d_in[2];
    const float* ab   = (const float*)d_in[3];
    const float* wk   = (const float*)d_in[4];  // (3,512,1,1) contiguous == (3,512)
    const float* bias = (const float*)d_in[5];
    float* out = (float*)d_out;

    // Kernel 1: 16384 warps -> 2048 blocks of 256 threads
    styles_kernel<<<2048, 256>>>(w, aw, ab);

    // Kernel 2 with programmatic dependent launch (overlap with kernel 1 tail)
    {
        cudaLaunchConfig_t cfg = {};
        cfg.gridDim  = dim3(HW4 / 256, BATCH, 1);
        cfg.blockDim = dim3(256, 1, 1);
        cfg.dynamicSmemBytes = 0;
        cfg.stream = 0;

        cudaLaunchAttribute attrs[1];
        attrs[0].id = cudaLaunchAttributeProgrammaticStreamSerialization;
        attrs[0].val.programmaticStreamSerializationAllowed = 1;
        cfg.attrs = attrs;
        cfg.numAttrs = 1;

        cudaLaunchKernelEx(&cfg, torgb_kernel, x, wk, bias, out);
    }
}

// round 7
// speedup vs baseline: 1.1775x; 1.0146x over previous
#include <cuda_runtime.h>
#include <math.h>

// Problem constants
#define W_DIM   512
#define IN_CH   512
#define OUT_CH  3
#define BATCH   32
#define HW      16384          // 128*128 pixels per (b, channel) plane
#define HW4     4096           // pixels / 4 (float4 granularity)
#define CLAMP_V 256.0f

#define TB      128            // torgb threads per block
#define SW_N    (OUT_CH * IN_CH)      // 1536
#define WK_PER_T (SW_N / TB)          // 12

// Scratch for per-(batch, channel) styles. 32*512 floats = 64 KB.
__device__ float g_styles[BATCH * IN_CH];

__device__ __forceinline__ float clampf(float v) {
    return fminf(fmaxf(v, -CLAMP_V), CLAMP_V);
}

// ---------------------------------------------------------------------------
// Kernel 1: styles[b,i] = (dot(w[b,:], aw[i,:]) * fc_gain + ab[i]) * weight_gain
// Fully parallel: one warp per (channel i, batch b) -> 16384 warps.
// ---------------------------------------------------------------------------
__global__ void __launch_bounds__(256) styles_kernel(
    const float* __restrict__ w,    // (32, 512)
    const float* __restrict__ aw,   // (512, 512)
    const float* __restrict__ ab)   // (512,)
{
    const int warp = (blockIdx.x * blockDim.x + threadIdx.x) >> 5;
    const int lane = threadIdx.x & 31;
    const int i = warp >> 5;           // channel 0..511
    const int b = warp & 31;           // batch   0..31

    if (i < IN_CH) {
        const float4* aw4 = (const float4*)(aw + (size_t)i * W_DIM);
        const float4* w4  = (const float4*)(w  + (size_t)b * W_DIM);

        float p = 0.0f;
#pragma unroll
        for (int c = 0; c < 4; c++) {
            float4 av = aw4[c * 32 + lane];
            float4 wv = w4[c * 32 + lane];
            p += av.x * wv.x + av.y * wv.y + av.z * wv.z + av.w * wv.w;
        }
#pragma unroll
        for (int off = 16; off; off >>= 1)
            p += __shfl_xor_sync(0xffffffffu, p, off);

        if (lane == 0) {
            const float fc_gain     = 1.0f / sqrtf((float)W_DIM);
            const float weight_gain = 1.0f / sqrtf((float)IN_CH);
            g_styles[b * IN_CH + i] = (p * fc_gain + ab[i]) * weight_gain;
        }
    }

    // Release the dependent (PDL) kernel as soon as our writes are done.
    cudaTriggerProgrammaticLaunchCompletion();
}

// ---------------------------------------------------------------------------
// Kernel 2: out[b,o,p] = clip( sum_i x[b,i,p] * (wk[o,i]*styles[b,i]) + bias[o] )
// 1024 blocks x 128 threads: 6.92 CTAs/SM -> last wave covers 92% of SMs
// (vs 46% with 512x256), recovering tail bandwidth. PDL overlaps launch +
// wk/bias register loads with styles_kernel; only the styles read sits
// after cudaGridDependencySynchronize().
// ---------------------------------------------------------------------------
__global__ void __launch_bounds__(TB) torgb_kernel(
    const float* __restrict__ x,     // (32, 512, 128, 128)
    const float* __restrict__ wk,    // (3, 512) -- weight[:,:,0,0] contiguous
    const float* __restrict__ bias,  // (3,)
    float*       __restrict__ out)   // (32, 3, 128, 128)
{
    __shared__ float sw[SW_N];   // 6 KB

    const int b = blockIdx.y;
    const int p = blockIdx.x * TB + threadIdx.x;   // 0..4095 float4 index
    const float4* xb = (const float4*)x + (size_t)b * IN_CH * HW4 + p;
    const float* st = g_styles + (size_t)b * IN_CH;

    // --- pre-sync prologue: everything independent of styles ---
    const float b0 = bias[0], b1 = bias[1], b2 = bias[2];
    float wkr[WK_PER_T];
#pragma unroll
    for (int k = 0; k < WK_PER_T; k++)
        wkr[k] = wk[k * TB + threadIdx.x];

    // Wait for styles_kernel's results before reading g_styles.
    cudaGridDependencySynchronize();

#pragma unroll
    for (int k = 0; k < WK_PER_T; k++) {
        int idx = k * TB + threadIdx.x;
        sw[idx] = wkr[k] * st[idx & (IN_CH - 1)];
    }
    __syncthreads();

    float4 a0 = {0.f, 0.f, 0.f, 0.f};
    float4 a1 = a0;
    float4 a2 = a0;

#pragma unroll 8
    for (int i = 0; i < IN_CH; i++) {
        float4 xv = xb[(size_t)i * HW4];
        float s0 = sw[i];
        float s1 = sw[IN_CH + i];
        float s2 = sw[2 * IN_CH + i];
        a0.x = fmaf(s0, xv.x, a0.x); a0.y = fmaf(s0, xv.y, a0.y);
        a0.z = fmaf(s0, xv.z, a0.z); a0.w = fmaf(s0, xv.w, a0.w);
        a1.x = fmaf(s1, xv.x, a1.x); a1.y = fmaf(s1, xv.y, a1.y);
        a1.z = fmaf(s1, xv.z, a1.z); a1.w = fmaf(s1, xv.w, a1.w);
        a2.x = fmaf(s2, xv.x, a2.x); a2.y = fmaf(s2, xv.y, a2.y);
        a2.z = fmaf(s2, xv.z, a2.z); a2.w = fmaf(s2, xv.w, a2.w);
    }

    float4 r0, r1, r2;
    r0.x = clampf(a0.x + b0); r0.y = clampf(a0.y + b0);
    r0.z = clampf(a0.z + b0); r0.w = clampf(a0.w + b0);
    r1.x = clampf(a1.x + b1); r1.y = clampf(a1.y + b1);
    r1.z = clampf(a1.z + b1); r1.w = clampf(a1.w + b1);
    r2.x = clampf(a2.x + b2); r2.y = clampf(a2.y + b2);
    r2.z = clampf(a2.z + b2); r2.w = clampf(a2.w + b2);

    float4* ob = (float4*)out + (size_t)b * OUT_CH * HW4 + p;
    ob[0]       = r0;
    ob[HW4]     = r1;
    ob[2 * HW4] = r2;
}

// ---------------------------------------------------------------------------
// kernel_launch
// Input order (metadata): x, w, affine_weight, affine_bias, weight, bias
// ---------------------------------------------------------------------------
extern "C" void kernel_launch(void* const* d_in, const int* in_sizes, int n_in,
                              void* d_out, int out_size)
{
    const float* x    = (const float*)d_in[0];
    const float* w    = (const float*)d_in[1];
    const float* aw   = (const float*)d_in[2];
    const float* ab   = (const float*)d_in[3];
    const float* wk   = (const float*)d_in[4];  // (3,512,1,1) contiguous == (3,512)
    const float* bias = (const float*)d_in[5];
    float* out = (float*)d_out;

    // Kernel 1: 16384 warps -> 2048 blocks of 256 threads
    styles_kernel<<<2048, 256>>>(w, aw, ab);

    // Kernel 2 with programmatic dependent launch (overlap with kernel 1 tail)
    {
        cudaLaunchConfig_t cfg = {};
        cfg.gridDim  = dim3(HW4 / TB, BATCH, 1);   // (32, 32) = 1024 blocks
        cfg.blockDim = dim3(TB, 1, 1);
        cfg.dynamicSmemBytes = 0;
        cfg.stream = 0;

        cudaLaunchAttribute attrs[1];
        attrs[0].id = cudaLaunchAttributeProgrammaticStreamSerialization;
        attrs[0].val.programmaticStreamSerializationAllowed = 1;
        cfg.attrs = attrs;
        cfg.numAttrs = 1;

        cudaLaunchKernelEx(&cfg, torgb_kernel, x, wk, bias, out);
    }
}

// round 9
// speedup vs baseline: 1.2070x; 1.0250x over previous
#include <cuda_runtime.h>
#include <math.h>

// Problem constants
#define W_DIM   512
#define IN_CH   512
#define OUT_CH  3
#define BATCH   32
#define HW      16384          // 128*128 pixels per (b, channel) plane
#define HW4     4096           // pixels / 4 (float4 granularity)
#define CLAMP_V 256.0f

#define TB      128            // torgb threads per block
#define SW_N    (OUT_CH * IN_CH)      // 1536
#define WK_PER_T (SW_N / TB)          // 12

// Scratch for per-(batch, channel) styles. 32*512 floats = 64 KB.
__device__ float g_styles[BATCH * IN_CH];

__device__ __forceinline__ float clampf(float v) {
    return fminf(fmaxf(v, -CLAMP_V), CLAMP_V);
}

// ---------------------------------------------------------------------------
// Kernel 1: styles[b,i] = (dot(w[b,:], aw[i,:]) * fc_gain + ab[i]) * weight_gain
// Warp per (channel i, batch-pair): 8192 warps. aw row loaded once per warp,
// reused for 2 batches -> half the redundant L1/L2 traffic of fully-parallel,
// same critical path to within ~100 cycles.
// ---------------------------------------------------------------------------
__global__ void __launch_bounds__(256) styles_kernel(
    const float* __restrict__ w,    // (32, 512)
    const float* __restrict__ aw,   // (512, 512)
    const float* __restrict__ ab)   // (512,)
{
    const int warp = (blockIdx.x * blockDim.x + threadIdx.x) >> 5;
    const int lane = threadIdx.x & 31;
    const int i  = warp >> 4;          // channel 0..511
    const int bp = warp & 15;          // batch pair 0..15

    if (i < IN_CH) {
        const float4* aw4 = (const float4*)(aw + (size_t)i * W_DIM);
        float4 av[4];
#pragma unroll
        for (int c = 0; c < 4; c++) av[c] = aw4[c * 32 + lane];

        const float fc_gain     = 1.0f / sqrtf((float)W_DIM);
        const float weight_gain = 1.0f / sqrtf((float)IN_CH);
        const float abi = ab[i];

#pragma unroll
        for (int bb = 0; bb < 2; bb++) {
            const int b = bp * 2 + bb;
            const float4* w4 = (const float4*)(w + (size_t)b * W_DIM);
            float p = 0.0f;
#pragma unroll
            for (int c = 0; c < 4; c++) {
                float4 wv = w4[c * 32 + lane];
                p += av[c].x * wv.x + av[c].y * wv.y + av[c].z * wv.z + av[c].w * wv.w;
            }
#pragma unroll
            for (int off = 16; off; off >>= 1)
                p += __shfl_xor_sync(0xffffffffu, p, off);
            if (lane == 0)
                g_styles[b * IN_CH + i] = (p * fc_gain + abi) * weight_gain;
        }
    }

    // Release the dependent (PDL) kernel as soon as our writes are done.
    cudaTriggerProgrammaticLaunchCompletion();
}

// ---------------------------------------------------------------------------
// Kernel 2: out[b,o,p] = clip( sum_i x[b,i,p] * (wk[o,i]*styles[b,i]) + bias[o] )
// 1024 blocks x 128 threads. x loaded with __ldcs (evict-first): strictly
// read-once data should not occupy L2 — frees LTS capacity for the stream.
// PDL overlaps launch + wk/bias loads with styles_kernel.
// ---------------------------------------------------------------------------
__global__ void __launch_bounds__(TB) torgb_kernel(
    const float* __restrict__ x,     // (32, 512, 128, 128)
    const float* __restrict__ wk,    // (3, 512) -- weight[:,:,0,0] contiguous
    const float* __restrict__ bias,  // (3,)
    float*       __restrict__ out)   // (32, 3, 128, 128)
{
    __shared__ float sw[SW_N];   // 6 KB

    const int b = blockIdx.y;
    const int p = blockIdx.x * TB + threadIdx.x;   // 0..4095 float4 index
    const float4* xb = (const float4*)x + (size_t)b * IN_CH * HW4 + p;
    const float* st = g_styles + (size_t)b * IN_CH;

    // --- pre-sync prologue: everything independent of styles ---
    const float b0 = bias[0], b1 = bias[1], b2 = bias[2];
    float wkr[WK_PER_T];
#pragma unroll
    for (int k = 0; k < WK_PER_T; k++)
        wkr[k] = wk[k * TB + threadIdx.x];

    // Wait for styles_kernel's results before reading g_styles.
    cudaGridDependencySynchronize();

#pragma unroll
    for (int k = 0; k < WK_PER_T; k++) {
        int idx = k * TB + threadIdx.x;
        sw[idx] = wkr[k] * st[idx & (IN_CH - 1)];
    }
    __syncthreads();

    float4 a0 = {0.f, 0.f, 0.f, 0.f};
    float4 a1 = a0;
    float4 a2 = a0;

#pragma unroll 8
    for (int i = 0; i < IN_CH; i++) {
        float4 xv = __ldcs(xb + (size_t)i * HW4);
        float s0 = sw[i];
        float s1 = sw[IN_CH + i];
        float s2 = sw[2 * IN_CH + i];
        a0.x = fmaf(s0, xv.x, a0.x); a0.y = fmaf(s0, xv.y, a0.y);
        a0.z = fmaf(s0, xv.z, a0.z); a0.w = fmaf(s0, xv.w, a0.w);
        a1.x = fmaf(s1, xv.x, a1.x); a1.y = fmaf(s1, xv.y, a1.y);
        a1.z = fmaf(s1, xv.z, a1.z); a1.w = fmaf(s1, xv.w, a1.w);
        a2.x = fmaf(s2, xv.x, a2.x); a2.y = fmaf(s2, xv.y, a2.y);
        a2.z = fmaf(s2, xv.z, a2.z); a2.w = fmaf(s2, xv.w, a2.w);
    }

    float4 r0, r1, r2;
    r0.x = clampf(a0.x + b0); r0.y = clampf(a0.y + b0);
    r0.z = clampf(a0.z + b0); r0.w = clampf(a0.w + b0);
    r1.x = clampf(a1.x + b1); r1.y = clampf(a1.y + b1);
    r1.z = clampf(a1.z + b1); r1.w = clampf(a1.w + b1);
    r2.x = clampf(a2.x + b2); r2.y = clampf(a2.y + b2);
    r2.z = clampf(a2.z + b2); r2.w = clampf(a2.w + b2);

    float4* ob = (float4*)out + (size_t)b * OUT_CH * HW4 + p;
    __stcs(ob,           r0);
    __stcs(ob + HW4,     r1);
    __stcs(ob + 2 * HW4, r2);
}

// ---------------------------------------------------------------------------
// kernel_launch
// Input order (metadata): x, w, affine_weight, affine_bias, weight, bias
// ---------------------------------------------------------------------------
extern "C" void kernel_launch(void* const* d_in, const int* in_sizes, int n_in,
                              void* d_out, int out_size)
{
    const float* x    = (const float*)d_in[0];
    const float* w    = (const float*)d_in[1];
    const float* aw   = (const float*)d_in[2];
    const float* ab   = (const float*)d_in[3];
    const float* wk   = (const float*)d_in[4];  // (3,512,1,1) contiguous == (3,512)
    const float* bias = (const float*)d_in[5];
    float* out = (float*)d_out;

    // Kernel 1: 8192 warps -> 1024 blocks of 256 threads
    styles_kernel<<<1024, 256>>>(w, aw, ab);

    // Kernel 2 with programmatic dependent launch (overlap with kernel 1 tail)
    {
        cudaLaunchConfig_t cfg = {};
        cfg.gridDim  = dim3(HW4 / TB, BATCH, 1);   // (32, 32) = 1024 blocks
        cfg.blockDim = dim3(TB, 1, 1);
        cfg.dynamicSmemBytes = 0;
        cfg.stream = 0;

        cudaLaunchAttribute attrs[1];
        attrs[0].id = cudaLaunchAttributeProgrammaticStreamSerialization;
        attrs[0].val.programmaticStreamSerializationAllowed = 1;
        cfg.attrs = attrs;
        cfg.numAttrs = 1;

        cudaLaunchKernelEx(&cfg, torgb_kernel, x, wk, bias, out);
    }
}